// round 11
// baseline (speedup 1.0000x reference)
#include <cuda_runtime.h>
#include <cuda_fp16.h>
#include <cstdint>
#include <cstddef>

// R11: HYBRID pipe LSTM (R10 with h-staging bug fixed: hr[8], full 64 halfs
// per thread staged, identical to R8's proven loader).
// GEMM split: legacy HMMA (k 64..127 + 256..383) + fma pipe HFMA2 k-pair
// dot products (k 0..63 + 128..255). 128 CTAs = 8 M-groups x 16 N-tiles.

#define SEQ   512
#define BATCH 512
#define DIM   128
#define HID   256
#define G4    1024
#define NCTA  128
#define NTHR  256
#define NGRP  16

#define SA_BYTES  49152            // A tile: 24 ks x 2048B
#define WF_OFF    SA_BYTES
#define WF_STRIDE 400              // bytes per col (96 pairs*4 + 16 pad)
#define WF_BYTES  (64 * WF_STRIDE) // 25600
#define SMEM_TOTAL (SA_BYTES + WF_BYTES)

// ---- persistent device scratch ----
__device__ __align__(16) __half g_h16[2][BATCH * HID];
__device__ __align__(128) unsigned long long g_bar_grp[8][16];

__device__ __forceinline__ uint32_t smem_u32(const void* p) {
    uint32_t a;
    asm("{ .reg .u64 t; cvta.to.shared.u64 t, %1; cvt.u32.u64 %0, t; }"
        : "=r"(a) : "l"(p));
    return a;
}
__device__ __forceinline__ void ldsm4(uint32_t a[4], uint32_t addr) {
    asm volatile("ldmatrix.sync.aligned.m8n8.x4.shared.b16 {%0,%1,%2,%3}, [%4];"
                 : "=r"(a[0]), "=r"(a[1]), "=r"(a[2]), "=r"(a[3]) : "r"(addr));
}
__device__ __forceinline__ void mma_f16acc(uint32_t c[2], const uint32_t a[4],
                                           uint32_t b0, uint32_t b1) {
    asm volatile(
        "mma.sync.aligned.m16n8k16.row.col.f16.f16.f16.f16 "
        "{%0,%1}, {%2,%3,%4,%5}, {%6,%7}, {%0,%1};"
        : "+r"(c[0]), "+r"(c[1])
        : "r"(a[0]), "r"(a[1]), "r"(a[2]), "r"(a[3]), "r"(b0), "r"(b1));
}
__device__ __forceinline__ void promote(float acc[4], uint32_t hc[2]) {
    float2 lo = __half22float2(*reinterpret_cast<__half2*>(&hc[0]));
    float2 hi = __half22float2(*reinterpret_cast<__half2*>(&hc[1]));
    acc[0] += lo.x; acc[1] += lo.y; acc[2] += hi.x; acc[3] += hi.y;
    hc[0] = 0u; hc[1] = 0u;
}
__device__ __forceinline__ float tanh_mufu(float x) {
    float y;
    asm("tanh.approx.f32 %0, %1;" : "=f"(y) : "f"(x));
    return y;
}
__device__ __forceinline__ float sig_mufu(float x) {
    return fmaf(0.5f, tanh_mufu(0.5f * x), 0.5f);
}
__device__ __forceinline__ uint32_t a_phys(int ks, int row, int kh) {
    return (uint32_t)(ks * 2048 + row * 32 + ((kh << 4) ^ ((row & 4) << 2)));
}

__global__ void __launch_bounds__(NTHR, 1)
lstm_hyb(const float* __restrict__ x,  const float* __restrict__ Wx,
         const float* __restrict__ Wh, const float* __restrict__ bv,
         const float* __restrict__ Wd, const float* __restrict__ bd,
         float* __restrict__ out)
{
    extern __shared__ __align__(1024) char smem[];
    char* sA  = smem;
    char* sWf = smem + WF_OFF;
    const uint32_t sA_u = smem_u32(sA);

    const int tid  = threadIdx.x;
    const int cta  = blockIdx.x;
    const int warp = tid >> 5, lane = tid & 31;
    const int grp = cta >> 4;
    const int r0 = grp * 64;
    const int j0 = (cta & 15) * 16;
    const int wM = warp & 1;            // 2-way M split (32 rows)
    const int wN = warp >> 1;           // 4-way N split (16 n-cols)
    unsigned long long* const bar_ctr = &g_bar_grp[grp][0];

    // ---- one-time: tensor-side B fragments (12 ks) into registers ----
    // bi 0..3 -> ks 4..7 (x k 64..127); bi 4..11 -> ks 16..23 (h k 256..383)
    uint32_t bfr[12][2][2];
    #pragma unroll
    for (int bi = 0; bi < 12; ++bi) {
        int ksg = (bi < 4) ? (4 + bi) : (16 + (bi - 4));
        #pragma unroll
        for (int nb = 0; nb < 2; ++nb) {
            int n = wN * 16 + nb * 8 + (lane >> 2);
            int col = (n & 3) * HID + j0 + (n >> 2);
            int k0 = ksg * 16 + (lane & 3) * 2;
            float w0, w1, w2, w3;
            if (k0 < DIM) {
                w0 = Wx[(size_t)k0 * G4 + col];
                w1 = Wx[(size_t)(k0 + 1) * G4 + col];
                w2 = Wx[(size_t)(k0 + 8) * G4 + col];
                w3 = Wx[(size_t)(k0 + 9) * G4 + col];
            } else {
                w0 = Wh[(size_t)(k0 - DIM) * G4 + col];
                w1 = Wh[(size_t)(k0 - DIM + 1) * G4 + col];
                w2 = Wh[(size_t)(k0 - DIM + 8) * G4 + col];
                w3 = Wh[(size_t)(k0 - DIM + 9) * G4 + col];
            }
            union { __half2 h; uint32_t u; } p0, p1;
            p0.h = __floats2half2_rn(w0, w1);
            p1.h = __floats2half2_rn(w2, w3);
            bfr[bi][nb][0] = p0.u;
            bfr[bi][nb][1] = p1.u;
        }
    }

    // ---- one-time: fma-side weights into sWf [col][pair] fp16 ----
    // kf 0..63 -> k=kf (x); kf 64..191 -> k=64+kf (h k 128..255)
    for (int idx = tid; idx < 64 * 192; idx += NTHR) {
        int kf = idx >> 6, n = idx & 63;
        int k = (kf < 64) ? kf : (64 + kf);
        int col = (n & 3) * HID + j0 + (n >> 2);
        float w = (k < DIM) ? Wx[(size_t)k * G4 + col]
                            : Wh[(size_t)(k - DIM) * G4 + col];
        *(__half*)(sWf + n * WF_STRIDE + (kf >> 1) * 4 + (kf & 1) * 2) =
            __float2half_rn(w);
    }

    // zero h buffer 0
    ((uint2*)g_h16[0])[cta * NTHR + tid] = make_uint2(0u, 0u);

    // epilogue geometry (R8)
    const int q = lane & 3;
    const int myOdd = lane & 1;
    const int rA = wM * 32 + myOdd * 16 + (lane >> 2);
    float bI[2], bF[2], bG[2], bO[2];
    #pragma unroll
    for (int nb = 0; nb < 2; ++nb) {
        int j = j0 + wN * 4 + nb * 2 + (q >> 1);
        bI[nb] = bv[j];
        bF[nb] = bv[HID + j];
        bG[nb] = bv[2 * HID + j];
        bO[nb] = bv[3 * HID + j];
    }
    float cst[4] = {0.f, 0.f, 0.f, 0.f};

    // fma-side per-thread coords: 4 rows x 4 cols matching MMA fragments
    int Rr[4], cloc[4];
    #pragma unroll
    for (int rj = 0; rj < 4; ++rj) Rr[rj] = wM * 32 + (lane >> 2) + rj * 8;
    cloc[0] = wN * 16 + 2 * q;     cloc[1] = cloc[0] + 1;
    cloc[2] = wN * 16 + 8 + 2 * q; cloc[3] = cloc[2] + 1;

    // loader coords (R8)
    const int xrow = tid >> 2, xkb = (tid & 3) * 32;
    const int hkb  = (tid & 3) * 64;

    const int lrow = lane & 15, lkh = lane >> 4;
    uint32_t lds0 = sA_u + a_phys(0, wM * 32 + lrow, lkh);
    uint32_t lds1 = sA_u + a_phys(0, wM * 32 + 16 + lrow, lkh);

    // ---- prologue: stage x(0) ----
    {
        const float* xp = x + ((size_t)(r0 + xrow) * SEQ + 0) * DIM + xkb;
        #pragma unroll
        for (int c2 = 0; c2 < 4; ++c2) {
            float4 v0 = *(const float4*)(xp + c2 * 8);
            float4 v1 = *(const float4*)(xp + c2 * 8 + 4);
            union { __half2 h; uint32_t u; } q0, q1, q2, q3;
            q0.h = __floats2half2_rn(v0.x, v0.y);
            q1.h = __floats2half2_rn(v0.z, v0.w);
            q2.h = __floats2half2_rn(v1.x, v1.y);
            q3.h = __floats2half2_rn(v1.z, v1.w);
            int k = xkb + c2 * 8;
            *(uint4*)(sA + a_phys(k >> 4, xrow, (k >> 3) & 1)) =
                make_uint4(q0.u, q1.u, q2.u, q3.u);
        }
    }

    // full group barrier once
    {
        __syncthreads();
        if (tid == 0) {
            __threadfence();
            unsigned long long t = atomicAdd(bar_ctr, 1ULL) + 1ULL;
            unsigned long long target =
                ((t + (unsigned long long)NGRP - 1ULL) / NGRP) *
                (unsigned long long)NGRP;
            unsigned long long v;
            do {
                asm volatile("ld.acquire.gpu.u64 %0, [%1];"
                             : "=l"(v) : "l"(bar_ctr) : "memory");
            } while (v < target);
        }
        __syncthreads();
    }

    const __half2 hz = __floats2half2_rn(0.f, 0.f);

    for (int s = 0; s < SEQ; ++s) {
        // h loads first (L1-bypass); hide under x-region compute.
        // FULL row coverage: 8 x uint4 = 64 halfs per thread (R8 loader).
        const __half* hp = g_h16[s & 1];
        const uint4* hsrc = (const uint4*)(hp + (size_t)(r0 + xrow) * HID + hkb);
        uint4 hr[8];
        #pragma unroll
        for (int c = 0; c < 8; ++c) hr[c] = __ldcv(hsrc + c);

        float acc[2][2][4];
        uint32_t hc[2][2][2];
        __half2 d2[4][4];
        #pragma unroll
        for (int mb = 0; mb < 2; ++mb)
            #pragma unroll
            for (int nb = 0; nb < 2; ++nb) {
                #pragma unroll
                for (int k = 0; k < 4; ++k) acc[mb][nb][k] = 0.f;
                hc[mb][nb][0] = 0u; hc[mb][nb][1] = 0u;
            }
        #pragma unroll
        for (int rj = 0; rj < 4; ++rj)
            #pragma unroll
            for (int cj = 0; cj < 4; ++cj) d2[rj][cj] = hz;

        auto tensor_ks = [&](int ks, int bi) {
            uint32_t am0[4], am1[4];
            ldsm4(am0, lds0 + ks * 2048);
            ldsm4(am1, lds1 + ks * 2048);
            mma_f16acc(hc[0][0], am0, bfr[bi][0][0], bfr[bi][0][1]);
            mma_f16acc(hc[0][1], am0, bfr[bi][1][0], bfr[bi][1][1]);
            mma_f16acc(hc[1][0], am1, bfr[bi][0][0], bfr[bi][0][1]);
            mma_f16acc(hc[1][1], am1, bfr[bi][1][0], bfr[bi][1][1]);
        };
        auto fma8 = [&](int ksA, int pwBase) {   // 8 k-pairs of one ks block
            #pragma unroll
            for (int pi = 0; pi < 8; ++pi) {
                const int kh = pi >> 2, io = (pi & 3) * 4;
                __half2 a2[4], w2[4];
                #pragma unroll
                for (int rj = 0; rj < 4; ++rj)
                    a2[rj] = *(const __half2*)(sA + ksA * 2048 + Rr[rj] * 32 +
                              ((kh << 4) ^ ((Rr[rj] & 4) << 2)) + io);
                #pragma unroll
                for (int cj = 0; cj < 4; ++cj)
                    w2[cj] = *(const __half2*)(sWf + cloc[cj] * WF_STRIDE +
                                               (pwBase + pi) * 4);
                #pragma unroll
                for (int rj = 0; rj < 4; ++rj)
                    #pragma unroll
                    for (int cj = 0; cj < 4; ++cj)
                        d2[rj][cj] = __hfma2(a2[rj], w2[cj], d2[rj][cj]);
            }
        };
        auto promote_d2 = [&]() {
            #pragma unroll
            for (int rj = 0; rj < 4; ++rj)
                #pragma unroll
                for (int cj = 0; cj < 4; ++cj) {
                    acc[rj >> 1][cj >> 1][((rj & 1) << 1) | (cj & 1)] +=
                        __low2float(d2[rj][cj]) + __high2float(d2[rj][cj]);
                    d2[rj][cj] = hz;
                }
        };

        // -- x region: tensor ks 4..7, fma pairs 0..31 (k 0..63)
        for (int g = 0; g < 4; ++g) {
            tensor_ks(4 + g, g);
            fma8(g, g * 8);
        }
        promote(acc[0][0], hc[0][0]); promote(acc[0][1], hc[0][1]);
        promote(acc[1][0], hc[1][0]); promote(acc[1][1], hc[1][1]);
        promote_d2();

        // -- stage h (full 64 halfs per thread)
        #pragma unroll
        for (int c = 0; c < 8; ++c) {
            int kg = DIM + hkb + c * 8;
            *(uint4*)(sA + a_phys(kg >> 4, xrow, (kg >> 3) & 1)) = hr[c];
        }
        __syncthreads();

        // -- h region: tensor ks 16..23, fma pairs 32..95 (k 128..255)
        for (int g = 0; g < 4; ++g) {
            tensor_ks(16 + g, 4 + g);
            fma8(8 + g, 32 + g * 8);
        }
        promote(acc[0][0], hc[0][0]); promote(acc[0][1], hc[0][1]);
        promote(acc[1][0], hc[1][0]); promote(acc[1][1], hc[1][1]);
        promote_d2();
        for (int g = 4; g < 8; ++g) {
            tensor_ks(16 + g, 4 + g);
            fma8(8 + g, 32 + g * 8);
        }
        promote(acc[0][0], hc[0][0]); promote(acc[0][1], hc[0][1]);
        promote(acc[1][0], hc[1][0]); promote(acc[1][1], hc[1][1]);
        promote_d2();

        // -- gate exchange (R8)
        float zif[2][4], zgo[2][4];
        #pragma unroll
        for (int nb = 0; nb < 2; ++nb)
            #pragma unroll
            for (int k = 0; k < 4; ++k) {
                float s0 = __shfl_xor_sync(0xffffffffu, acc[0][nb][k], 1);
                float s1 = __shfl_xor_sync(0xffffffffu, acc[1][nb][k], 1);
                zif[nb][k] = myOdd ? s1 : acc[0][nb][k];
                zgo[nb][k] = myOdd ? acc[1][nb][k] : s0;
            }

        __half* hn = g_h16[(s + 1) & 1];
        #pragma unroll
        for (int nb = 0; nb < 2; ++nb) {
            int j = j0 + wN * 4 + nb * 2 + (q >> 1);
            float i0 = sig_mufu(zif[nb][0] + bI[nb]);
            float f0 = sig_mufu(zif[nb][1] + bF[nb]);
            float g0 = tanh_mufu(zgo[nb][0] + bG[nb]);
            float o0 = sig_mufu(zgo[nb][1] + bO[nb]);
            float i1 = sig_mufu(zif[nb][2] + bI[nb]);
            float f1 = sig_mufu(zif[nb][3] + bF[nb]);
            float g1 = tanh_mufu(zgo[nb][2] + bG[nb]);
            float o1 = sig_mufu(zgo[nb][3] + bO[nb]);
            cst[nb * 2 + 0] = f0 * cst[nb * 2 + 0] + i0 * g0;
            cst[nb * 2 + 1] = f1 * cst[nb * 2 + 1] + i1 * g1;
            hn[(size_t)(r0 + rA) * HID + j] =
                __float2half_rn(o0 * tanh_mufu(cst[nb * 2 + 0]));
            hn[(size_t)(r0 + rA + 8) * HID + j] =
                __float2half_rn(o1 * tanh_mufu(cst[nb * 2 + 1]));
        }

        // -- split barrier: arrive, stage x(s+1) in the window, wait
        __syncthreads();
        unsigned long long tick = 0;
        if (tid == 0) {
            asm volatile("atom.add.release.gpu.global.u64 %0, [%1], 1;"
                         : "=l"(tick) : "l"(bar_ctr) : "memory");
            tick += 1ULL;
        }
        if (s + 1 < SEQ) {
            const float* xp = x + ((size_t)(r0 + xrow) * SEQ + (s + 1)) * DIM + xkb;
            #pragma unroll
            for (int c2 = 0; c2 < 4; ++c2) {
                float4 v0 = *(const float4*)(xp + c2 * 8);
                float4 v1 = *(const float4*)(xp + c2 * 8 + 4);
                union { __half2 h; uint32_t u; } q0, q1, q2, q3;
                q0.h = __floats2half2_rn(v0.x, v0.y);
                q1.h = __floats2half2_rn(v0.z, v0.w);
                q2.h = __floats2half2_rn(v1.x, v1.y);
                q3.h = __floats2half2_rn(v1.z, v1.w);
                int k = xkb + c2 * 8;
                *(uint4*)(sA + a_phys(k >> 4, xrow, (k >> 3) & 1)) =
                    make_uint4(q0.u, q1.u, q2.u, q3.u);
            }
        }
        if (tid == 0) {
            unsigned long long target =
                ((tick + (unsigned long long)NGRP - 1ULL) / NGRP) *
                (unsigned long long)NGRP;
            unsigned long long v;
            do {
                asm volatile("ld.acquire.gpu.u64 %0, [%1];"
                             : "=l"(v) : "l"(bar_ctr) : "memory");
            } while (v < target);
        }
        __syncthreads();
    }

    // ---- classifier + softmax (R8) ----
    if (warp < 4) {
        const int row = cta * 4 + warp;
        const __half* hf = g_h16[0];
        float acc10[10];
        #pragma unroll
        for (int c = 0; c < 10; ++c) acc10[c] = 0.f;
        uint4 hv = __ldcv((const uint4*)(hf + (size_t)row * HID + lane * 8));
        const __half* hvh = (const __half*)&hv;
        #pragma unroll
        for (int u = 0; u < 8; ++u) {
            float h = __half2float(hvh[u]);
            const float* wd = Wd + (size_t)(lane * 8 + u) * 10;
            #pragma unroll
            for (int c = 0; c < 10; ++c) acc10[c] += h * wd[c];
        }
        #pragma unroll
        for (int off = 16; off > 0; off >>= 1) {
            #pragma unroll
            for (int c = 0; c < 10; ++c)
                acc10[c] += __shfl_down_sync(0xffffffffu, acc10[c], off);
        }
        if (lane == 0) {
            float m = -3.0e38f;
            #pragma unroll
            for (int c = 0; c < 10; ++c) { acc10[c] += bd[c]; m = fmaxf(m, acc10[c]); }
            float ssum = 0.f;
            #pragma unroll
            for (int c = 0; c < 10; ++c) { acc10[c] = __expf(acc10[c] - m); ssum += acc10[c]; }
            float inv = 1.0f / ssum;
            #pragma unroll
            for (int c = 0; c < 10; ++c) out[(size_t)row * 10 + c] = acc10[c] * inv;
        }
    }
}

extern "C" void kernel_launch(void* const* d_in, const int* in_sizes, int n_in,
                              void* d_out, int out_size) {
    const float* x  = (const float*)d_in[0];
    const float* Wx = (const float*)d_in[1];
    const float* Wh = (const float*)d_in[2];
    const float* b  = (const float*)d_in[3];
    const float* Wd = (const float*)d_in[4];
    const float* bd = (const float*)d_in[5];
    (void)in_sizes; (void)n_in; (void)out_size;
    cudaFuncSetAttribute(lstm_hyb, cudaFuncAttributeMaxDynamicSharedMemorySize,
                         SMEM_TOTAL);
    lstm_hyb<<<NCTA, NTHR, SMEM_TOTAL>>>(x, Wx, Wh, b, Wd, bd, (float*)d_out);
}

// round 12
// speedup vs baseline: 1.6425x; 1.6425x over previous
#include <cuda_runtime.h>
#include <cuda_fp16.h>
#include <cstdint>
#include <cstddef>

// R12: HYBRID pipe LSTM = R11 with the phase loops FULLY UNROLLED.
// R11's regression was local-memory spill: un-unrolled `for (g)` loops made
// bfr/d2/Rr/cloc runtime-indexed -> demoted to local (regs 254->168, L1 60%).
// All indices are now compile-time. GEMM split: legacy HMMA (k 64..127 +
// 256..383) + fma-pipe HFMA2 k-pair dots (k 0..63 + 128..255).
// 128 CTAs = 8 M-groups(64 rows) x 16 N-tiles(16 jl x 4 gates).

#define SEQ   512
#define BATCH 512
#define DIM   128
#define HID   256
#define G4    1024
#define NCTA  128
#define NTHR  256
#define NGRP  16

#define SA_BYTES  49152            // A tile: 24 ks x 2048B
#define WF_OFF    SA_BYTES
#define WF_STRIDE 400              // bytes per col (96 pairs*4 + 16 pad)
#define WF_BYTES  (64 * WF_STRIDE) // 25600
#define SMEM_TOTAL (SA_BYTES + WF_BYTES)

// ---- persistent device scratch ----
__device__ __align__(16) __half g_h16[2][BATCH * HID];
__device__ __align__(128) unsigned long long g_bar_grp[8][16];

__device__ __forceinline__ uint32_t smem_u32(const void* p) {
    uint32_t a;
    asm("{ .reg .u64 t; cvta.to.shared.u64 t, %1; cvt.u32.u64 %0, t; }"
        : "=r"(a) : "l"(p));
    return a;
}
__device__ __forceinline__ void ldsm4(uint32_t a[4], uint32_t addr) {
    asm volatile("ldmatrix.sync.aligned.m8n8.x4.shared.b16 {%0,%1,%2,%3}, [%4];"
                 : "=r"(a[0]), "=r"(a[1]), "=r"(a[2]), "=r"(a[3]) : "r"(addr));
}
__device__ __forceinline__ void mma_f16acc(uint32_t c[2], const uint32_t a[4],
                                           uint32_t b0, uint32_t b1) {
    asm volatile(
        "mma.sync.aligned.m16n8k16.row.col.f16.f16.f16.f16 "
        "{%0,%1}, {%2,%3,%4,%5}, {%6,%7}, {%0,%1};"
        : "+r"(c[0]), "+r"(c[1])
        : "r"(a[0]), "r"(a[1]), "r"(a[2]), "r"(a[3]), "r"(b0), "r"(b1));
}
__device__ __forceinline__ void promote(float acc[4], uint32_t hc[2]) {
    float2 lo = __half22float2(*reinterpret_cast<__half2*>(&hc[0]));
    float2 hi = __half22float2(*reinterpret_cast<__half2*>(&hc[1]));
    acc[0] += lo.x; acc[1] += lo.y; acc[2] += hi.x; acc[3] += hi.y;
    hc[0] = 0u; hc[1] = 0u;
}
__device__ __forceinline__ float tanh_mufu(float x) {
    float y;
    asm("tanh.approx.f32 %0, %1;" : "=f"(y) : "f"(x));
    return y;
}
__device__ __forceinline__ float sig_mufu(float x) {
    return fmaf(0.5f, tanh_mufu(0.5f * x), 0.5f);
}
__device__ __forceinline__ uint32_t a_phys(int ks, int row, int kh) {
    return (uint32_t)(ks * 2048 + row * 32 + ((kh << 4) ^ ((row & 4) << 2)));
}

__global__ void __launch_bounds__(NTHR, 1)
lstm_hyb(const float* __restrict__ x,  const float* __restrict__ Wx,
         const float* __restrict__ Wh, const float* __restrict__ bv,
         const float* __restrict__ Wd, const float* __restrict__ bd,
         float* __restrict__ out)
{
    extern __shared__ __align__(1024) char smem[];
    char* sA  = smem;
    char* sWf = smem + WF_OFF;
    const uint32_t sA_u = smem_u32(sA);

    const int tid  = threadIdx.x;
    const int cta  = blockIdx.x;
    const int warp = tid >> 5, lane = tid & 31;
    const int grp = cta >> 4;
    const int r0 = grp * 64;
    const int j0 = (cta & 15) * 16;
    const int wM = warp & 1;            // 2-way M split (32 rows)
    const int wN = warp >> 1;           // 4-way N split (16 n-cols)
    unsigned long long* const bar_ctr = &g_bar_grp[grp][0];

    // ---- one-time: tensor-side B fragments (12 ks) into registers ----
    // bi 0..3 -> ks 4..7 (x k 64..127); bi 4..11 -> ks 16..23 (h k 256..383)
    uint32_t bfr[12][2][2];
    #pragma unroll
    for (int bi = 0; bi < 12; ++bi) {
        int ksg = (bi < 4) ? (4 + bi) : (16 + (bi - 4));
        #pragma unroll
        for (int nb = 0; nb < 2; ++nb) {
            int n = wN * 16 + nb * 8 + (lane >> 2);
            int col = (n & 3) * HID + j0 + (n >> 2);
            int k0 = ksg * 16 + (lane & 3) * 2;
            float w0, w1, w2, w3;
            if (k0 < DIM) {
                w0 = Wx[(size_t)k0 * G4 + col];
                w1 = Wx[(size_t)(k0 + 1) * G4 + col];
                w2 = Wx[(size_t)(k0 + 8) * G4 + col];
                w3 = Wx[(size_t)(k0 + 9) * G4 + col];
            } else {
                w0 = Wh[(size_t)(k0 - DIM) * G4 + col];
                w1 = Wh[(size_t)(k0 - DIM + 1) * G4 + col];
                w2 = Wh[(size_t)(k0 - DIM + 8) * G4 + col];
                w3 = Wh[(size_t)(k0 - DIM + 9) * G4 + col];
            }
            union { __half2 h; uint32_t u; } p0, p1;
            p0.h = __floats2half2_rn(w0, w1);
            p1.h = __floats2half2_rn(w2, w3);
            bfr[bi][nb][0] = p0.u;
            bfr[bi][nb][1] = p1.u;
        }
    }

    // ---- one-time: fma-side weights into sWf [col][pair] fp16 ----
    // kf 0..63 -> k=kf (x); kf 64..191 -> k=64+kf (h k 128..255)
    for (int idx = tid; idx < 64 * 192; idx += NTHR) {
        int kf = idx >> 6, n = idx & 63;
        int k = (kf < 64) ? kf : (64 + kf);
        int col = (n & 3) * HID + j0 + (n >> 2);
        float w = (k < DIM) ? Wx[(size_t)k * G4 + col]
                            : Wh[(size_t)(k - DIM) * G4 + col];
        *(__half*)(sWf + n * WF_STRIDE + (kf >> 1) * 4 + (kf & 1) * 2) =
            __float2half_rn(w);
    }

    // zero h buffer 0
    ((uint2*)g_h16[0])[cta * NTHR + tid] = make_uint2(0u, 0u);

    // epilogue geometry (R8)
    const int q = lane & 3;
    const int myOdd = lane & 1;
    const int rA = wM * 32 + myOdd * 16 + (lane >> 2);
    float bI[2], bF[2], bG[2], bO[2];
    #pragma unroll
    for (int nb = 0; nb < 2; ++nb) {
        int j = j0 + wN * 4 + nb * 2 + (q >> 1);
        bI[nb] = bv[j];
        bF[nb] = bv[HID + j];
        bG[nb] = bv[2 * HID + j];
        bO[nb] = bv[3 * HID + j];
    }
    float cst[4] = {0.f, 0.f, 0.f, 0.f};

    // fma-side per-thread coords: 4 rows x 4 cols matching MMA fragments
    int Rr[4], cloc[4];
    #pragma unroll
    for (int rj = 0; rj < 4; ++rj) Rr[rj] = wM * 32 + (lane >> 2) + rj * 8;
    cloc[0] = wN * 16 + 2 * q;     cloc[1] = cloc[0] + 1;
    cloc[2] = wN * 16 + 8 + 2 * q; cloc[3] = cloc[2] + 1;

    // loader coords (R8)
    const int xrow = tid >> 2, xkb = (tid & 3) * 32;
    const int hkb  = (tid & 3) * 64;

    const int lrow = lane & 15, lkh = lane >> 4;
    uint32_t lds0 = sA_u + a_phys(0, wM * 32 + lrow, lkh);
    uint32_t lds1 = sA_u + a_phys(0, wM * 32 + 16 + lrow, lkh);

    // ---- prologue: stage x(0) ----
    {
        const float* xp = x + ((size_t)(r0 + xrow) * SEQ + 0) * DIM + xkb;
        #pragma unroll
        for (int c2 = 0; c2 < 4; ++c2) {
            float4 v0 = *(const float4*)(xp + c2 * 8);
            float4 v1 = *(const float4*)(xp + c2 * 8 + 4);
            union { __half2 h; uint32_t u; } q0, q1, q2, q3;
            q0.h = __floats2half2_rn(v0.x, v0.y);
            q1.h = __floats2half2_rn(v0.z, v0.w);
            q2.h = __floats2half2_rn(v1.x, v1.y);
            q3.h = __floats2half2_rn(v1.z, v1.w);
            int k = xkb + c2 * 8;
            *(uint4*)(sA + a_phys(k >> 4, xrow, (k >> 3) & 1)) =
                make_uint4(q0.u, q1.u, q2.u, q3.u);
        }
    }

    // full group barrier once
    {
        __syncthreads();
        if (tid == 0) {
            __threadfence();
            unsigned long long t = atomicAdd(bar_ctr, 1ULL) + 1ULL;
            unsigned long long target =
                ((t + (unsigned long long)NGRP - 1ULL) / NGRP) *
                (unsigned long long)NGRP;
            unsigned long long v;
            do {
                asm volatile("ld.acquire.gpu.u64 %0, [%1];"
                             : "=l"(v) : "l"(bar_ctr) : "memory");
            } while (v < target);
        }
        __syncthreads();
    }

    const __half2 hz = __floats2half2_rn(0.f, 0.f);

    for (int s = 0; s < SEQ; ++s) {
        // h loads first (L1-bypass); hide under x-region compute.
        const __half* hp = g_h16[s & 1];
        const uint4* hsrc = (const uint4*)(hp + (size_t)(r0 + xrow) * HID + hkb);
        uint4 hr[8];
        #pragma unroll
        for (int c = 0; c < 8; ++c) hr[c] = __ldcv(hsrc + c);

        float acc[2][2][4];
        uint32_t hc[2][2][2];
        __half2 d2[4][4];
        #pragma unroll
        for (int mb = 0; mb < 2; ++mb)
            #pragma unroll
            for (int nb = 0; nb < 2; ++nb) {
                #pragma unroll
                for (int k = 0; k < 4; ++k) acc[mb][nb][k] = 0.f;
                hc[mb][nb][0] = 0u; hc[mb][nb][1] = 0u;
            }
        #pragma unroll
        for (int rj = 0; rj < 4; ++rj)
            #pragma unroll
            for (int cj = 0; cj < 4; ++cj) d2[rj][cj] = hz;

        auto tensor_ks = [&](int ks, int bi) {
            uint32_t am0[4], am1[4];
            ldsm4(am0, lds0 + ks * 2048);
            ldsm4(am1, lds1 + ks * 2048);
            mma_f16acc(hc[0][0], am0, bfr[bi][0][0], bfr[bi][0][1]);
            mma_f16acc(hc[0][1], am0, bfr[bi][1][0], bfr[bi][1][1]);
            mma_f16acc(hc[1][0], am1, bfr[bi][0][0], bfr[bi][0][1]);
            mma_f16acc(hc[1][1], am1, bfr[bi][1][0], bfr[bi][1][1]);
        };
        auto fma8 = [&](int ksA, int pwBase) {   // 8 k-pairs of one ks block
            #pragma unroll
            for (int pi = 0; pi < 8; ++pi) {
                const int kh = pi >> 2, io = (pi & 3) * 4;
                __half2 a2[4], w2[4];
                #pragma unroll
                for (int rj = 0; rj < 4; ++rj)
                    a2[rj] = *(const __half2*)(sA + ksA * 2048 + Rr[rj] * 32 +
                              ((kh << 4) ^ ((Rr[rj] & 4) << 2)) + io);
                #pragma unroll
                for (int cj = 0; cj < 4; ++cj)
                    w2[cj] = *(const __half2*)(sWf + cloc[cj] * WF_STRIDE +
                                               (pwBase + pi) * 4);
                #pragma unroll
                for (int rj = 0; rj < 4; ++rj)
                    #pragma unroll
                    for (int cj = 0; cj < 4; ++cj)
                        d2[rj][cj] = __hfma2(a2[rj], w2[cj], d2[rj][cj]);
            }
        };
        auto promote_d2 = [&]() {
            #pragma unroll
            for (int rj = 0; rj < 4; ++rj)
                #pragma unroll
                for (int cj = 0; cj < 4; ++cj) {
                    acc[rj >> 1][cj >> 1][((rj & 1) << 1) | (cj & 1)] +=
                        __low2float(d2[rj][cj]) + __high2float(d2[rj][cj]);
                    d2[rj][cj] = hz;
                }
        };

        // -- x region: tensor ks 4..7, fma pairs 0..31 (k 0..63)
        #pragma unroll
        for (int g = 0; g < 4; ++g) {
            tensor_ks(4 + g, g);
            fma8(g, g * 8);
        }
        promote(acc[0][0], hc[0][0]); promote(acc[0][1], hc[0][1]);
        promote(acc[1][0], hc[1][0]); promote(acc[1][1], hc[1][1]);
        promote_d2();

        // -- stage h (full 64 halfs per thread)
        #pragma unroll
        for (int c = 0; c < 8; ++c) {
            int kg = DIM + hkb + c * 8;
            *(uint4*)(sA + a_phys(kg >> 4, xrow, (kg >> 3) & 1)) = hr[c];
        }
        __syncthreads();

        // -- h region: tensor ks 16..23, fma pairs 32..95 (k 128..255)
        #pragma unroll
        for (int g = 0; g < 4; ++g) {
            tensor_ks(16 + g, 4 + g);
            fma8(8 + g, 32 + g * 8);
        }
        promote(acc[0][0], hc[0][0]); promote(acc[0][1], hc[0][1]);
        promote(acc[1][0], hc[1][0]); promote(acc[1][1], hc[1][1]);
        promote_d2();
        #pragma unroll
        for (int g = 4; g < 8; ++g) {
            tensor_ks(16 + g, 4 + g);
            fma8(8 + g, 32 + g * 8);
        }
        promote(acc[0][0], hc[0][0]); promote(acc[0][1], hc[0][1]);
        promote(acc[1][0], hc[1][0]); promote(acc[1][1], hc[1][1]);
        promote_d2();

        // -- gate exchange (R8)
        float zif[2][4], zgo[2][4];
        #pragma unroll
        for (int nb = 0; nb < 2; ++nb)
            #pragma unroll
            for (int k = 0; k < 4; ++k) {
                float s0 = __shfl_xor_sync(0xffffffffu, acc[0][nb][k], 1);
                float s1 = __shfl_xor_sync(0xffffffffu, acc[1][nb][k], 1);
                zif[nb][k] = myOdd ? s1 : acc[0][nb][k];
                zgo[nb][k] = myOdd ? acc[1][nb][k] : s0;
            }

        __half* hn = g_h16[(s + 1) & 1];
        #pragma unroll
        for (int nb = 0; nb < 2; ++nb) {
            int j = j0 + wN * 4 + nb * 2 + (q >> 1);
            float i0 = sig_mufu(zif[nb][0] + bI[nb]);
            float f0 = sig_mufu(zif[nb][1] + bF[nb]);
            float g0 = tanh_mufu(zgo[nb][0] + bG[nb]);
            float o0 = sig_mufu(zgo[nb][1] + bO[nb]);
            float i1 = sig_mufu(zif[nb][2] + bI[nb]);
            float f1 = sig_mufu(zif[nb][3] + bF[nb]);
            float g1 = tanh_mufu(zgo[nb][2] + bG[nb]);
            float o1 = sig_mufu(zgo[nb][3] + bO[nb]);
            cst[nb * 2 + 0] = f0 * cst[nb * 2 + 0] + i0 * g0;
            cst[nb * 2 + 1] = f1 * cst[nb * 2 + 1] + i1 * g1;
            hn[(size_t)(r0 + rA) * HID + j] =
                __float2half_rn(o0 * tanh_mufu(cst[nb * 2 + 0]));
            hn[(size_t)(r0 + rA + 8) * HID + j] =
                __float2half_rn(o1 * tanh_mufu(cst[nb * 2 + 1]));
        }

        // -- split barrier: arrive, stage x(s+1) in the window, wait
        __syncthreads();
        unsigned long long tick = 0;
        if (tid == 0) {
            asm volatile("atom.add.release.gpu.global.u64 %0, [%1], 1;"
                         : "=l"(tick) : "l"(bar_ctr) : "memory");
            tick += 1ULL;
        }
        if (s + 1 < SEQ) {
            const float* xp = x + ((size_t)(r0 + xrow) * SEQ + (s + 1)) * DIM + xkb;
            #pragma unroll
            for (int c2 = 0; c2 < 4; ++c2) {
                float4 v0 = *(const float4*)(xp + c2 * 8);
                float4 v1 = *(const float4*)(xp + c2 * 8 + 4);
                union { __half2 h; uint32_t u; } q0, q1, q2, q3;
                q0.h = __floats2half2_rn(v0.x, v0.y);
                q1.h = __floats2half2_rn(v0.z, v0.w);
                q2.h = __floats2half2_rn(v1.x, v1.y);
                q3.h = __floats2half2_rn(v1.z, v1.w);
                int k = xkb + c2 * 8;
                *(uint4*)(sA + a_phys(k >> 4, xrow, (k >> 3) & 1)) =
                    make_uint4(q0.u, q1.u, q2.u, q3.u);
            }
        }
        if (tid == 0) {
            unsigned long long target =
                ((tick + (unsigned long long)NGRP - 1ULL) / NGRP) *
                (unsigned long long)NGRP;
            unsigned long long v;
            do {
                asm volatile("ld.acquire.gpu.u64 %0, [%1];"
                             : "=l"(v) : "l"(bar_ctr) : "memory");
            } while (v < target);
        }
        __syncthreads();
    }

    // ---- classifier + softmax (R8) ----
    if (warp < 4) {
        const int row = cta * 4 + warp;
        const __half* hf = g_h16[0];
        float acc10[10];
        #pragma unroll
        for (int c = 0; c < 10; ++c) acc10[c] = 0.f;
        uint4 hv = __ldcv((const uint4*)(hf + (size_t)row * HID + lane * 8));
        const __half* hvh = (const __half*)&hv;
        #pragma unroll
        for (int u = 0; u < 8; ++u) {
            float h = __half2float(hvh[u]);
            const float* wd = Wd + (size_t)(lane * 8 + u) * 10;
            #pragma unroll
            for (int c = 0; c < 10; ++c) acc10[c] += h * wd[c];
        }
        #pragma unroll
        for (int off = 16; off > 0; off >>= 1) {
            #pragma unroll
            for (int c = 0; c < 10; ++c)
                acc10[c] += __shfl_down_sync(0xffffffffu, acc10[c], off);
        }
        if (lane == 0) {
            float m = -3.0e38f;
            #pragma unroll
            for (int c = 0; c < 10; ++c) { acc10[c] += bd[c]; m = fmaxf(m, acc10[c]); }
            float ssum = 0.f;
            #pragma unroll
            for (int c = 0; c < 10; ++c) { acc10[c] = __expf(acc10[c] - m); ssum += acc10[c]; }
            float inv = 1.0f / ssum;
            #pragma unroll
            for (int c = 0; c < 10; ++c) out[(size_t)row * 10 + c] = acc10[c] * inv;
        }
    }
}

extern "C" void kernel_launch(void* const* d_in, const int* in_sizes, int n_in,
                              void* d_out, int out_size) {
    const float* x  = (const float*)d_in[0];
    const float* Wx = (const float*)d_in[1];
    const float* Wh = (const float*)d_in[2];
    const float* b  = (const float*)d_in[3];
    const float* Wd = (const float*)d_in[4];
    const float* bd = (const float*)d_in[5];
    (void)in_sizes; (void)n_in; (void)out_size;
    cudaFuncSetAttribute(lstm_hyb, cudaFuncAttributeMaxDynamicSharedMemorySize,
                         SMEM_TOTAL);
    lstm_hyb<<<NCTA, NTHR, SMEM_TOTAL>>>(x, Wx, Wh, b, Wd, bd, (float*)d_out);
}